// round 2
// baseline (speedup 1.0000x reference)
#include <cuda_runtime.h>
#include <cstdint>

#define NSUP 131072
#define DD   512
#define CC   1024
#define LL   3
#define ROWS 64
#define KB   32
#define NCHUNK (DD / KB)

// ---------------- device scratch (static: no runtime allocation) ----------------
__device__ float g_Xs[(size_t)NSUP * DD];   // label-sorted copy of support_features
__device__ int   g_cls[NSUP];               // class of each sorted row
__device__ int   g_counts[CC];
__device__ int   g_cursor[CC];
__device__ int   g_off[CC];
__device__ float g_S[LL * CC * DD];         // per-level class sums of g = relu(LN(X@W1+b1))

// ---------------- helpers ----------------
__device__ __forceinline__ void cp_async16(void* sdst, const void* gsrc) {
    unsigned s = (unsigned)__cvta_generic_to_shared(sdst);
    asm volatile("cp.async.cg.shared.global [%0], [%1], 16;" :: "r"(s), "l"(gsrc));
}
__device__ __forceinline__ void cp_commit() { asm volatile("cp.async.commit_group;"); }
__device__ __forceinline__ void cp_wait1()  { asm volatile("cp.async.wait_group 1;"); }
__device__ __forceinline__ void cp_wait0()  { asm volatile("cp.async.wait_group 0;"); }

__device__ __forceinline__ unsigned long long fma2(unsigned long long a,
                                                   unsigned long long b,
                                                   unsigned long long c) {
    unsigned long long d;
    asm("fma.rn.f32x2 %0, %1, %2, %3;" : "=l"(d) : "l"(a), "l"(b), "l"(c));
    return d;
}
__device__ __forceinline__ unsigned long long pack2(float x, float y) {
    unsigned long long d;
    asm("mov.b64 %0, {%1, %2};" : "=l"(d) : "f"(x), "f"(y));
    return d;
}
__device__ __forceinline__ float2 unpack2(unsigned long long v) {
    float2 f;
    asm("mov.b64 {%0, %1}, %2;" : "=f"(f.x), "=f"(f.y) : "l"(v));
    return f;
}

// ---------------- small kernels ----------------
__global__ void zero_kernel() {
    int i = blockIdx.x * 256 + threadIdx.x;
    if (i < LL * CC * DD) g_S[i] = 0.f;
    if (i < CC) { g_counts[i] = 0; g_cursor[i] = 0; }
}

__global__ void hist_kernel(const int* __restrict__ labels) {
    int i = blockIdx.x * 256 + threadIdx.x;
    if (i < NSUP) atomicAdd(&g_counts[labels[i]], 1);
}

__global__ void scan_kernel() {
    __shared__ int tmp[CC];
    int t = threadIdx.x;
    int v = g_counts[t];
    tmp[t] = v;
    __syncthreads();
    for (int o = 1; o < CC; o <<= 1) {
        int add = (t >= o) ? tmp[t - o] : 0;
        __syncthreads();
        tmp[t] += add;
        __syncthreads();
    }
    g_off[t] = tmp[t] - v;  // exclusive prefix
}

// one warp per row: stable-ish scatter of X rows into class-sorted order
__global__ void scatter_kernel(const float* __restrict__ X, const int* __restrict__ labels) {
    int row  = blockIdx.x * 8 + (threadIdx.x >> 5);
    int lane = threadIdx.x & 31;
    int c = labels[row];
    int pos = 0;
    if (lane == 0) pos = g_off[c] + atomicAdd(&g_cursor[c], 1);
    pos = __shfl_sync(0xffffffffu, pos, 0);
    if (lane == 0) g_cls[pos] = c;
    const float4* src = (const float4*)(X + (size_t)row * DD);
    float4* dst = (float4*)(g_Xs + (size_t)pos * DD);
#pragma unroll
    for (int i = 0; i < 4; i++) dst[lane + 32 * i] = src[lane + 32 * i];
}

// ---------------- main fused kernel ----------------
// Per CTA: 64 sorted rows x full D=512. GEMM (X@W1) with f32x2 FMAs,
// +b1, LayerNorm, ReLU, class-segment reduce, atomic into g_S[level].
// smem: As[2][64][32] (4096 f) | Bs[2][32][512] (32768 f, reused as H[64][512])
//       | gamma[512] beta[512] b1[512] | cls[64]
#define LVL_SMEM_BYTES (size_t)((4096 + 32768 + 1536) * 4 + 64 * 4)

__global__ __launch_bounds__(512, 1)
void level_kernel(const float* __restrict__ W1, const float* __restrict__ b1,
                  const float* __restrict__ gamma, const float* __restrict__ beta)
{
    extern __shared__ float sm[];
    float* As  = sm;                   // [2][64][32] row-major [row][k]
    float* Bs  = sm + 4096;            // [2][32][512] row-major [k][col]
    float* H   = Bs;                   // overlay after GEMM: [64][512]
    float* gms = sm + 4096 + 32768;
    float* bts = gms + 512;
    float* b1s = bts + 512;
    int*   clss = (int*)(b1s + 512);

    const int l = blockIdx.y;
    const int row0 = blockIdx.x * ROWS;
    const int tid = threadIdx.x;
    const float* W = W1 + (size_t)l * DD * DD;
    float* Sl = g_S + (size_t)l * CC * DD;

    gms[tid] = gamma[l * DD + tid];
    bts[tid] = beta[l * DD + tid];
    b1s[tid] = b1[l * DD + tid];
    if (tid < ROWS) clss[tid] = g_cls[row0 + tid];

    const int c_t = tid & 63;   // 64 col-groups x 8 cols (4 + 4 at +256)
    const int r_t = tid >> 6;   // 8 row-groups x 8 rows
    const int arow = tid >> 3, akk = (tid & 7) << 2;

    // prologue: chunk 0
    cp_async16(&As[arow * 32 + akk], &g_Xs[(size_t)(row0 + arow) * DD + akk]);
#pragma unroll
    for (int i = 0; i < 8; i++) {
        int idx = tid + i * 512;
        int k = idx >> 7, c4 = (idx & 127) << 2;
        cp_async16(&Bs[k * 512 + c4], &W[(size_t)k * DD + c4]);
    }
    cp_commit();

    unsigned long long acc[8][4];
#pragma unroll
    for (int i = 0; i < 8; i++)
#pragma unroll
        for (int j = 0; j < 4; j++) acc[i][j] = 0ULL;

    for (int ch = 0; ch < NCHUNK; ch++) {
        const int nb = ch & 1;
        if (ch + 1 < NCHUNK) {
            const int k0 = (ch + 1) * KB;
            const int dbuf = nb ^ 1;
            cp_async16(&As[dbuf * 2048 + arow * 32 + akk],
                       &g_Xs[(size_t)(row0 + arow) * DD + k0 + akk]);
#pragma unroll
            for (int i = 0; i < 8; i++) {
                int idx = tid + i * 512;
                int k = idx >> 7, c4 = (idx & 127) << 2;
                cp_async16(&Bs[dbuf * 16384 + k * 512 + c4], &W[(size_t)(k0 + k) * DD + c4]);
            }
            cp_commit();
            cp_wait1();
        } else {
            cp_wait0();
        }
        __syncthreads();

        const float* Ab = As + nb * 2048;
        const float* Bb = Bs + nb * 16384;
#pragma unroll 8
        for (int k = 0; k < KB; k++) {
            ulonglong2 bA = *(const ulonglong2*)(Bb + k * 512 + (c_t << 2));
            ulonglong2 bB = *(const ulonglong2*)(Bb + k * 512 + 256 + (c_t << 2));
#pragma unroll
            for (int i = 0; i < 8; i++) {
                float a = Ab[(r_t * 8 + i) * 32 + k];
                unsigned long long ap = pack2(a, a);
                acc[i][0] = fma2(ap, bA.x, acc[i][0]);
                acc[i][1] = fma2(ap, bA.y, acc[i][1]);
                acc[i][2] = fma2(ap, bB.x, acc[i][2]);
                acc[i][3] = fma2(ap, bB.y, acc[i][3]);
            }
        }
        __syncthreads();
    }

    // ---- epilogue: H = acc + b1 (overlay Bs) ----
    const int c0 = c_t << 2;
#pragma unroll
    for (int i = 0; i < 8; i++) {
        int row = r_t * 8 + i;
        float2 p0 = unpack2(acc[i][0]), p1 = unpack2(acc[i][1]);
        float2 p2 = unpack2(acc[i][2]), p3 = unpack2(acc[i][3]);
        float4 v0, v1;
        v0.x = p0.x + b1s[c0];         v0.y = p0.y + b1s[c0 + 1];
        v0.z = p1.x + b1s[c0 + 2];     v0.w = p1.y + b1s[c0 + 3];
        v1.x = p2.x + b1s[256 + c0];   v1.y = p2.y + b1s[256 + c0 + 1];
        v1.z = p3.x + b1s[256 + c0 + 2]; v1.w = p3.y + b1s[256 + c0 + 3];
        *(float4*)(H + row * 512 + c0) = v0;
        *(float4*)(H + row * 512 + 256 + c0) = v1;
    }
    __syncthreads();

    // ---- LayerNorm + ReLU: warp w handles rows 4w..4w+3 ----
    const int warp = tid >> 5, lane = tid & 31;
#pragma unroll
    for (int rr = 0; rr < 4; rr++) {
        int row = warp * 4 + rr;
        float s = 0.f, s2 = 0.f;
#pragma unroll
        for (int j = 0; j < 16; j++) {
            float v = H[row * 512 + lane + j * 32];
            s += v; s2 += v * v;
        }
#pragma unroll
        for (int o = 16; o; o >>= 1) {
            s  += __shfl_xor_sync(0xffffffffu, s, o);
            s2 += __shfl_xor_sync(0xffffffffu, s2, o);
        }
        float mu = s * (1.f / 512.f);
        float var = s2 * (1.f / 512.f) - mu * mu;
        float rstd = rsqrtf(var + 1e-5f);
#pragma unroll
        for (int j = 0; j < 16; j++) {
            int col = lane + j * 32;
            float v = H[row * 512 + col];
            float g = (v - mu) * rstd * gms[col] + bts[col];
            H[row * 512 + col] = fmaxf(g, 0.f);
        }
    }
    __syncthreads();

    // ---- class-segment reduce (rows are label-sorted) + atomic to global ----
    {
        int col = tid;  // 512 threads == 512 cols
        float sum = 0.f;
        int cur = clss[0];
#pragma unroll 4
        for (int r = 0; r < ROWS; r++) {
            int c2 = clss[r];
            if (c2 != cur) {
                atomicAdd(&Sl[(size_t)cur * DD + col], sum);
                sum = 0.f; cur = c2;
            }
            sum += H[r * 512 + col];
        }
        atomicAdd(&Sl[(size_t)cur * DD + col], sum);
    }
}

// ---------------- finalize: out = sum_l w_l * ((S_l/cnt) @ W2_l) + [cnt>0]*sum_l w_l*b2_l
// tile: 16 classes x 512 cols, K=512, 3 levels folded (w_l/cnt folded into A)
#define FIN_SMEM_BYTES (size_t)((512 + 16384) * 4)

__global__ __launch_bounds__(512, 1)
void finalize_kernel(const float* __restrict__ W2, const float* __restrict__ b2,
                     const float* __restrict__ temps, float* __restrict__ out)
{
    extern __shared__ float sm[];
    float* As = sm;         // [16][32]
    float* Bs = sm + 512;   // [32][512]
    const int tid = threadIdx.x;
    const int row0 = blockIdx.x * 16;
    const int c_t = tid & 63, r_t = tid >> 6;

    float t0 = temps[0], t1 = temps[1], t2 = temps[2];
    float mx = fmaxf(t0, fmaxf(t1, t2));
    float e0 = expf(t0 - mx), e1 = expf(t1 - mx), e2 = expf(t2 - mx);
    float inv = 1.f / (e0 + e1 + e2);
    float w[3] = {e0 * inv, e1 * inv, e2 * inv};

    unsigned long long acc[2][4];
#pragma unroll
    for (int i = 0; i < 2; i++)
#pragma unroll
        for (int j = 0; j < 4; j++) acc[i][j] = 0ULL;

    for (int l = 0; l < LL; l++) {
        for (int ch = 0; ch < NCHUNK; ch++) {
            __syncthreads();
            {
                int row = tid >> 5, kk = tid & 31;
                int cl = row0 + row;
                float cnt = fmaxf((float)g_counts[cl], 1.f);
                As[row * 32 + kk] =
                    g_S[(size_t)l * CC * DD + (size_t)cl * DD + ch * KB + kk] * (w[l] / cnt);
            }
#pragma unroll
            for (int i = 0; i < 8; i++) {
                int idx = tid + i * 512;
                int k = idx >> 7, c4 = (idx & 127) << 2;
                *(float4*)(Bs + k * 512 + c4) =
                    *(const float4*)(W2 + (size_t)l * DD * DD + (size_t)(ch * KB + k) * DD + c4);
            }
            __syncthreads();
#pragma unroll 8
            for (int k = 0; k < KB; k++) {
                ulonglong2 bA = *(const ulonglong2*)(Bs + k * 512 + (c_t << 2));
                ulonglong2 bB = *(const ulonglong2*)(Bs + k * 512 + 256 + (c_t << 2));
#pragma unroll
                for (int i = 0; i < 2; i++) {
                    float a = As[(r_t * 2 + i) * 32 + k];
                    unsigned long long ap = pack2(a, a);
                    acc[i][0] = fma2(ap, bA.x, acc[i][0]);
                    acc[i][1] = fma2(ap, bA.y, acc[i][1]);
                    acc[i][2] = fma2(ap, bB.x, acc[i][2]);
                    acc[i][3] = fma2(ap, bB.y, acc[i][3]);
                }
            }
        }
    }

    const int c0 = c_t << 2;
#pragma unroll
    for (int i = 0; i < 2; i++) {
        int cl = row0 + r_t * 2 + i;
        float has = (g_counts[cl] > 0) ? 1.f : 0.f;
        float2 p0 = unpack2(acc[i][0]), p1 = unpack2(acc[i][1]);
        float2 p2 = unpack2(acc[i][2]), p3 = unpack2(acc[i][3]);
        float4 v0, v1;
        v0.x = p0.x + has * (w[0] * b2[c0]       + w[1] * b2[DD + c0]       + w[2] * b2[2 * DD + c0]);
        v0.y = p0.y + has * (w[0] * b2[c0 + 1]   + w[1] * b2[DD + c0 + 1]   + w[2] * b2[2 * DD + c0 + 1]);
        v0.z = p1.x + has * (w[0] * b2[c0 + 2]   + w[1] * b2[DD + c0 + 2]   + w[2] * b2[2 * DD + c0 + 2]);
        v0.w = p1.y + has * (w[0] * b2[c0 + 3]   + w[1] * b2[DD + c0 + 3]   + w[2] * b2[2 * DD + c0 + 3]);
        int c1 = 256 + c0;
        v1.x = p2.x + has * (w[0] * b2[c1]       + w[1] * b2[DD + c1]       + w[2] * b2[2 * DD + c1]);
        v1.y = p2.y + has * (w[0] * b2[c1 + 1]   + w[1] * b2[DD + c1 + 1]   + w[2] * b2[2 * DD + c1 + 1]);
        v1.z = p3.x + has * (w[0] * b2[c1 + 2]   + w[1] * b2[DD + c1 + 2]   + w[2] * b2[2 * DD + c1 + 2]);
        v1.w = p3.y + has * (w[0] * b2[c1 + 3]   + w[1] * b2[DD + c1 + 3]   + w[2] * b2[2 * DD + c1 + 3]);
        *(float4*)(out + (size_t)cl * DD + c0) = v0;
        *(float4*)(out + (size_t)cl * DD + c1) = v1;
    }
}

// ---------------- launch ----------------
extern "C" void kernel_launch(void* const* d_in, const int* in_sizes, int n_in,
                              void* d_out, int out_size)
{
    const float* X      = (const float*)d_in[0];
    const int*   labels = (const int*)d_in[1];
    const float* W1     = (const float*)d_in[2];
    const float* b1     = (const float*)d_in[3];
    const float* gamma  = (const float*)d_in[4];
    const float* beta   = (const float*)d_in[5];
    const float* W2     = (const float*)d_in[6];
    const float* b2     = (const float*)d_in[7];
    const float* temps  = (const float*)d_in[8];
    float* out = (float*)d_out;

    cudaFuncSetAttribute(level_kernel, cudaFuncAttributeMaxDynamicSharedMemorySize,
                         (int)LVL_SMEM_BYTES);
    cudaFuncSetAttribute(finalize_kernel, cudaFuncAttributeMaxDynamicSharedMemorySize,
                         (int)FIN_SMEM_BYTES);

    zero_kernel<<<(LL * CC * DD + 255) / 256, 256>>>();
    hist_kernel<<<(NSUP + 255) / 256, 256>>>(labels);
    scan_kernel<<<1, CC>>>();
    scatter_kernel<<<NSUP / 8, 256>>>(X, labels);
    level_kernel<<<dim3(NSUP / ROWS, LL), 512, LVL_SMEM_BYTES>>>(W1, b1, gamma, beta);
    finalize_kernel<<<CC / 16, 512, FIN_SMEM_BYTES>>>(W2, b2, temps, out);
}